// round 8
// baseline (speedup 1.0000x reference)
#include <cuda_runtime.h>
#include <cuda_fp16.h>
#include <cstdint>

#define NODES 50000
#define F 64
#define E_MAX 2000000
#define SBS 512
#define SNB ((NODES + SBS - 1) / SBS)   // 98

// ---------------- scratch (device globals; no allocations allowed) ----------
__device__ float4 g_agg4[NODES * (F / 4)];   // [NODES,64] mean-aggregated feats
__device__ float4 g_h4[NODES * (F / 4)];     // [NODES,64] layer-1 output (fp32)
__device__ __half g_xh[NODES * F];           // fp16 copy of x   (gather feed)
__device__ __half g_hh[NODES * F];           // fp16 copy of h   (gather feed)
__device__ int    g_is32;                    // 1 if edge indices are int32

__device__ int g_cnt0[NODES], g_cnt1[NODES];
__device__ int g_rowptr0[NODES + 1], g_rowptr1[NODES + 1];
__device__ int g_rank0[E_MAX], g_rank1[E_MAX];   // intra-node edge ranks
__device__ int g_csr0[E_MAX], g_csr1[E_MAX];

// decoupled-lookback scan state, per set (reset by prep each replay)
__device__ unsigned long long g_tail0[SNB], g_tail1[SNB];
__device__ unsigned int g_ticket0, g_ticket1;

// ---------------- f32x2 packed-FMA helpers (FFMA2, sm_100+) ------------------
__device__ __forceinline__ unsigned long long pk2(float a) {
    unsigned long long r;
    asm("mov.b64 %0, {%1, %1};" : "=l"(r) : "f"(a));
    return r;
}
__device__ __forceinline__ void fma2(unsigned long long& d,
                                     unsigned long long a,
                                     unsigned long long b) {
    asm("fma.rn.f32x2 %0, %1, %2, %0;" : "+l"(d) : "l"(a), "l"(b));
}
__device__ __forceinline__ float2 up2(unsigned long long v) {
    float2 f;
    asm("mov.b64 {%0, %1}, %2;" : "=f"(f.x), "=f"(f.y) : "l"(v));
    return f;
}

// ---------------- prep: sniff + zero counts/scan-state + x->fp16 -------------
__global__ void prep_kernel(const long long* __restrict__ e0,
                            const float* __restrict__ x) {
    int i = blockIdx.x * blockDim.x + threadIdx.x;
    if (blockIdx.x == 0) {
        long long v = e0[threadIdx.x];
        int bad = (v < 0 || v >= (long long)NODES) ? 1 : 0;
        bad = __syncthreads_or(bad);
        if (threadIdx.x == 0) g_is32 = bad;
    }
    if (i < NODES) { g_cnt0[i] = 0; g_cnt1[i] = 0; }
    if (i < SNB) { g_tail0[i] = 0ull; g_tail1[i] = 0ull; }
    if (i == 0) { g_ticket0 = 0u; g_ticket1 = 0u; }
    if (i < NODES * (F / 4)) {
        float4 v = ((const float4*)x)[i];
        union { __half2 h[2]; uint2 u; } cv;
        cv.h[0] = __floats2half2_rn(v.x, v.y);
        cv.h[1] = __floats2half2_rn(v.z, v.w);
        ((uint2*)g_xh)[i] = cv.u;
    }
}

// ---------------- count one layer + record intra-node ranks (8 edges/thr) ---
template <int SET>
__global__ void count_set_kernel(const void* __restrict__ ei, int E) {
    int* cnt = SET ? g_cnt1 : g_cnt0;
    int* rank = SET ? g_rank1 : g_rank0;
    int t = blockIdx.x * blockDim.x + threadIdx.x;
    int base = t * 8;
    if (base >= E) return;
    if (base + 8 <= E) {
        int c[8];
        if (g_is32) {
            const int* p = (const int*)ei + E;
            int4 a = __ldg((const int4*)p + 2 * t);
            int4 b = __ldg((const int4*)p + 2 * t + 1);
            c[0] = a.x; c[1] = a.y; c[2] = a.z; c[3] = a.w;
            c[4] = b.x; c[5] = b.y; c[6] = b.z; c[7] = b.w;
        } else {
            const long long* p = (const long long*)ei + E;
#pragma unroll
            for (int k = 0; k < 4; k++) {
                longlong2 v = __ldg((const longlong2*)p + 4 * t + k);
                c[2 * k] = (int)v.x; c[2 * k + 1] = (int)v.y;
            }
        }
        int rk[8];
#pragma unroll
        for (int k = 0; k < 8; k++) rk[k] = atomicAdd(&cnt[c[k]], 1);
        int4 w0 = make_int4(rk[0], rk[1], rk[2], rk[3]);
        int4 w1 = make_int4(rk[4], rk[5], rk[6], rk[7]);
        *((int4*)rank + 2 * t) = w0;
        *((int4*)rank + 2 * t + 1) = w1;
    } else {
        for (int k = 0; k < E - base; k++) {
            int cc;
            if (g_is32) cc = __ldg((const int*)ei + E + base + k);
            else        cc = (int)__ldg((const long long*)ei + E + base + k);
            rank[base + k] = atomicAdd(&cnt[cc], 1);
        }
    }
}

// ---------------- single-pass scan (decoupled lookback), one set ------------
template <int SET>
__global__ void __launch_bounds__(SBS) scan_set_kernel() {
    const int* cnt = SET ? g_cnt1 : g_cnt0;
    int* rowptr = SET ? g_rowptr1 : g_rowptr0;
    unsigned long long* tail = SET ? g_tail1 : g_tail0;
    unsigned int* ticket = SET ? &g_ticket1 : &g_ticket0;

    __shared__ int sh_bid;
    __shared__ int sh_total;
    __shared__ long long sh_pref;
    __shared__ int ws[SBS / 32];
    int tid = threadIdx.x;
    if (tid == 0) sh_bid = (int)atomicAdd(ticket, 1u);
    __syncthreads();
    int j = sh_bid;

    int i = j * SBS + tid;
    int v = (i < NODES) ? cnt[i] : 0;
    int lane = tid & 31, warp = tid >> 5;
    int x = v;
#pragma unroll
    for (int o = 1; o < 32; o <<= 1) {
        int y = __shfl_up_sync(0xFFFFFFFFu, x, o);
        if (lane >= o) x += y;
    }
    if (lane == 31) ws[warp] = x;
    __syncthreads();
    if (warp == 0) {
        int s = (lane < SBS / 32) ? ws[lane] : 0;
#pragma unroll
        for (int o = 1; o < 32; o <<= 1) {
            int y = __shfl_up_sync(0xFFFFFFFFu, s, o);
            if (lane >= o) s += y;
        }
        if (lane < SBS / 32) ws[lane] = s;
    }
    __syncthreads();
    if (warp > 0) x += ws[warp - 1];
    if (tid == SBS - 1) sh_total = x;
    __syncthreads();
    int total = sh_total;

    if (tid == 0) {
        if (j == 0) {
            atomicExch(&tail[0], (2ull << 62) | (unsigned long long)total);
            sh_pref = 0;
        } else {
            atomicExch(&tail[j], (1ull << 62) | (unsigned long long)total);
            long long p = 0;
            int k = j - 1;
            while (true) {
                unsigned long long tv = atomicAdd(&tail[k], 0ull);
                unsigned st = (unsigned)(tv >> 62);
                if (st == 0) continue;        // not yet published; spin
                p += (long long)(tv & 0x3FFFFFFFFFFFFFFFull);
                if (st == 2) break;           // inclusive prefix reached
                --k;
            }
            atomicExch(&tail[j], (2ull << 62) | (unsigned long long)(p + total));
            sh_pref = p;
        }
    }
    __syncthreads();
    int pref = (int)sh_pref;
    if (i < NODES) rowptr[i + 1] = x + pref;
    if (i == 0) rowptr[0] = 0;
}

// ---------------- place one layer (atomic-free, rank-based, 8 edges/thr) ----
template <int SET>
__global__ void place_set_kernel(const void* __restrict__ ei, int E) {
    const int* rowptr = SET ? g_rowptr1 : g_rowptr0;
    const int* rank = SET ? g_rank1 : g_rank0;
    int* csr = SET ? g_csr1 : g_csr0;
    int t = blockIdx.x * blockDim.x + threadIdx.x;
    int base = t * 8;
    if (base >= E) return;
    if (base + 8 <= E) {
        int r[8], c[8];
        if (g_is32) {
            const int* p = (const int*)ei;
            int4 a = __ldg((const int4*)p + 2 * t);
            int4 b = __ldg((const int4*)p + 2 * t + 1);
            r[0] = a.x; r[1] = a.y; r[2] = a.z; r[3] = a.w;
            r[4] = b.x; r[5] = b.y; r[6] = b.z; r[7] = b.w;
            int4 d = __ldg((const int4*)(p + E) + 2 * t);
            int4 e = __ldg((const int4*)(p + E) + 2 * t + 1);
            c[0] = d.x; c[1] = d.y; c[2] = d.z; c[3] = d.w;
            c[4] = e.x; c[5] = e.y; c[6] = e.z; c[7] = e.w;
        } else {
            const long long* p = (const long long*)ei;
#pragma unroll
            for (int k = 0; k < 4; k++) {
                longlong2 v = __ldg((const longlong2*)p + 4 * t + k);
                r[2 * k] = (int)v.x; r[2 * k + 1] = (int)v.y;
            }
#pragma unroll
            for (int k = 0; k < 4; k++) {
                longlong2 v = __ldg((const longlong2*)(p + E) + 4 * t + k);
                c[2 * k] = (int)v.x; c[2 * k + 1] = (int)v.y;
            }
        }
        int4 rk0 = *((const int4*)rank + 2 * t);
        int4 rk1 = *((const int4*)rank + 2 * t + 1);
        int rk[8] = {rk0.x, rk0.y, rk0.z, rk0.w, rk1.x, rk1.y, rk1.z, rk1.w};
        int pos[8];
#pragma unroll
        for (int k = 0; k < 8; k++) pos[k] = __ldg(&rowptr[c[k]]) + rk[k];
#pragma unroll
        for (int k = 0; k < 8; k++) csr[pos[k]] = r[k];
    } else {
        for (int k = 0; k < E - base; k++) {
            int rr, cc;
            if (g_is32) {
                rr = __ldg((const int*)ei + base + k);
                cc = __ldg((const int*)ei + E + base + k);
            } else {
                rr = (int)__ldg((const long long*)ei + base + k);
                cc = (int)__ldg((const long long*)ei + E + base + k);
            }
            csr[__ldg(&rowptr[cc]) + rank[base + k]] = rr;
        }
    }
}

// ---------------- gather-side mean aggregation (fp16 feed, fp32 acc) --------
// one warp per node; each lane owns 2 columns (half2); unroll 8 for MLP
template <int SET>
__global__ void __launch_bounds__(256) gather_kernel(
    const __half* __restrict__ srch) {
    const int* rowptr = SET ? g_rowptr1 : g_rowptr0;
    const int* csr = SET ? g_csr1 : g_csr0;
    int tid = threadIdx.x;
    int node = blockIdx.x * 8 + (tid >> 5);
    if (node >= NODES) return;
    int lane = tid & 31;
    int s = __ldg(&rowptr[node]);
    int e = __ldg(&rowptr[node + 1]);
    float ax = 0.f, ay = 0.f;
    int i = s;
    for (; i + 8 <= e; i += 8) {
        int r[8];
#pragma unroll
        for (int k = 0; k < 8; k++) r[k] = __ldg(&csr[i + k]);
        float2 v[8];
#pragma unroll
        for (int k = 0; k < 8; k++)
            v[k] = __half22float2(*((const __half2*)(srch + (size_t)r[k] * F) + lane));
#pragma unroll
        for (int k = 0; k < 8; k++) { ax += v[k].x; ay += v[k].y; }
    }
    for (; i < e; i++) {
        int r = __ldg(&csr[i]);
        float2 v = __half22float2(*((const __half2*)(srch + (size_t)r * F) + lane));
        ax += v.x; ay += v.y;
    }
    float inv = 1.f / (float)max(e - s, 1);
    float2 o; o.x = ax * inv; o.y = ay * inv;
    *(float2*)((float*)g_agg4 + (size_t)node * F + lane * 2) = o;
}

// ---------------- fused dense: out = agg@W + b + xin@R ----------------------
// 128 nodes x 64 outputs, 256 threads, 8x4 blocking via packed FFMA2.
// RELU path additionally emits fp16 copy of the output into g_hh.
template <bool RELU, bool NORM>
__global__ void __launch_bounds__(256) dense_kernel(
    const float* __restrict__ xin,
    const float* __restrict__ W, const float* __restrict__ bias,
    const float* __restrict__ R, float* __restrict__ out, int n_nodes) {
    extern __shared__ float smem[];
    float* As = smem;                    // [64][132]
    float* Ws = smem + F * 132;          // [64][64]
    float* sb = Ws + F * F;              // [64]

    const float* agg = (const float*)g_agg4;
    int tid = threadIdx.x;
    int n0 = blockIdx.x * 128;

    if (tid < F) sb[tid] = bias[tid];

    unsigned long long acc2[8][2];
#pragma unroll
    for (int a = 0; a < 8; a++) { acc2[a][0] = 0ull; acc2[a][1] = 0ull; }

    int j0 = (tid & 15) * 4;
    int i0 = (tid >> 4) * 8;

#pragma unroll
    for (int c = 0; c < 2; ++c) {
        const float* src = c ? xin : agg;
        const float* wsrc = c ? R : W;
        __syncthreads();
#pragma unroll
        for (int t = 0; t < 8; ++t) {
            int q = tid + 256 * t;          // [0,2048)
            int i = q >> 4;                 // node within tile (0..127)
            int kk = (q & 15) << 2;         // k offset
            int n = n0 + i;
            float4 v = make_float4(0.f, 0.f, 0.f, 0.f);
            if (n < n_nodes) v = *(const float4*)(src + (size_t)n * F + kk);
            As[(kk + 0) * 132 + i] = v.x;
            As[(kk + 1) * 132 + i] = v.y;
            As[(kk + 2) * 132 + i] = v.z;
            As[(kk + 3) * 132 + i] = v.w;
        }
#pragma unroll
        for (int t = 0; t < 4; ++t) {
            int q = tid + 256 * t;          // [0,1024)
            *(float4*)(Ws + q * 4) = *(const float4*)(wsrc + q * 4);
        }
        __syncthreads();
#pragma unroll
        for (int k = 0; k < F; ++k) {
            float4 a0 = *(const float4*)&As[k * 132 + i0];
            float4 a1 = *(const float4*)&As[k * 132 + i0 + 4];
            ulonglong2 wv = *(const ulonglong2*)&Ws[k * F + j0];
            unsigned long long p;
            p = pk2(a0.x); fma2(acc2[0][0], p, wv.x); fma2(acc2[0][1], p, wv.y);
            p = pk2(a0.y); fma2(acc2[1][0], p, wv.x); fma2(acc2[1][1], p, wv.y);
            p = pk2(a0.z); fma2(acc2[2][0], p, wv.x); fma2(acc2[2][1], p, wv.y);
            p = pk2(a0.w); fma2(acc2[3][0], p, wv.x); fma2(acc2[3][1], p, wv.y);
            p = pk2(a1.x); fma2(acc2[4][0], p, wv.x); fma2(acc2[4][1], p, wv.y);
            p = pk2(a1.y); fma2(acc2[5][0], p, wv.x); fma2(acc2[5][1], p, wv.y);
            p = pk2(a1.z); fma2(acc2[6][0], p, wv.x); fma2(acc2[6][1], p, wv.y);
            p = pk2(a1.w); fma2(acc2[7][0], p, wv.x); fma2(acc2[7][1], p, wv.y);
        }
    }

    // epilogue
    float o[8][4];
#pragma unroll
    for (int ii = 0; ii < 8; ++ii) {
        float2 lo = up2(acc2[ii][0]);
        float2 hi = up2(acc2[ii][1]);
        o[ii][0] = lo.x + sb[j0 + 0];
        o[ii][1] = lo.y + sb[j0 + 1];
        o[ii][2] = hi.x + sb[j0 + 2];
        o[ii][3] = hi.y + sb[j0 + 3];
        if (RELU) {
            o[ii][0] = fmaxf(o[ii][0], 0.f); o[ii][1] = fmaxf(o[ii][1], 0.f);
            o[ii][2] = fmaxf(o[ii][2], 0.f); o[ii][3] = fmaxf(o[ii][3], 0.f);
        }
    }
    if (NORM) {
        // each row's 64 cols live in 16 lanes of one half-warp -> xor 1,2,4,8
#pragma unroll
        for (int ii = 0; ii < 8; ++ii) {
            float ss = o[ii][0] * o[ii][0] + o[ii][1] * o[ii][1] +
                       o[ii][2] * o[ii][2] + o[ii][3] * o[ii][3];
#pragma unroll
            for (int m = 1; m < 16; m <<= 1)
                ss += __shfl_xor_sync(0xFFFFFFFFu, ss, m);
            float inv = 1.f / fmaxf(sqrtf(ss), 1e-12f);
            o[ii][0] *= inv; o[ii][1] *= inv;
            o[ii][2] *= inv; o[ii][3] *= inv;
        }
    }
#pragma unroll
    for (int ii = 0; ii < 8; ++ii) {
        int n = n0 + i0 + ii;
        if (n < n_nodes) {
            float4 v = make_float4(o[ii][0], o[ii][1], o[ii][2], o[ii][3]);
            *(float4*)(out + (size_t)n * F + j0) = v;
            if (RELU) {   // fp16 copy for the next gather
                union { __half2 h[2]; uint2 u; } cv;
                cv.h[0] = __floats2half2_rn(o[ii][0], o[ii][1]);
                cv.h[1] = __floats2half2_rn(o[ii][2], o[ii][3]);
                *(uint2*)(g_hh + (size_t)n * F + j0) = cv.u;
            }
        }
    }
}

// ---------------- launch -----------------------------------------------------
extern "C" void kernel_launch(void* const* d_in, const int* in_sizes, int n_in,
                              void* d_out, int out_size) {
    const float* x  = (const float*)d_in[0];
    const void*  e0 = d_in[1];
    const void*  e1 = d_in[2];
    const float* W1 = (const float*)d_in[3];
    const float* b1 = (const float*)d_in[4];
    const float* R1 = (const float*)d_in[5];
    const float* W2 = (const float*)d_in[6];
    const float* b2 = (const float*)d_in[7];
    const float* R2 = (const float*)d_in[8];
    float* out = (float*)d_out;

    static float* h4 = nullptr;
    static __half* xh = nullptr;
    static __half* hh = nullptr;
    static cudaStream_t s2;
    static cudaEvent_t evA, evB;
    if (!h4) {
        void* p;
        cudaGetSymbolAddress(&p, g_h4); h4 = (float*)p;
        cudaGetSymbolAddress(&p, g_xh); xh = (__half*)p;
        cudaGetSymbolAddress(&p, g_hh); hh = (__half*)p;
        cudaStreamCreateWithFlags(&s2, cudaStreamNonBlocking);
        cudaEventCreateWithFlags(&evA, cudaEventDisableTiming);
        cudaEventCreateWithFlags(&evB, cudaEventDisableTiming);
        cudaFuncSetAttribute(dense_kernel<true, false>,
                             cudaFuncAttributeMaxDynamicSharedMemorySize, 51200);
        cudaFuncSetAttribute(dense_kernel<false, true>,
                             cudaFuncAttributeMaxDynamicSharedMemorySize, 51200);
    }

    int E = in_sizes[1] / 2;
    int n_nodes = out_size / F;              // 50000
    int dsmem = (F * 132 + F * F + F) * 4;   // 50432 B

    int cb = ((E + 7) / 8 + 255) / 256;
    int pb = (NODES * F / 4 + 255) / 256;
    int gb = (NODES + 7) / 8;
    int db = (n_nodes + 127) / 128;

    prep_kernel<<<pb, 256>>>((const long long*)e0, x);

    // fork: layer-2 CSR build on stream B, overlapped with layer-1 pipeline
    cudaEventRecord(evA, 0);
    cudaStreamWaitEvent(s2, evA, 0);
    count_set_kernel<1><<<cb, 256, 0, s2>>>(e1, E);
    scan_set_kernel<1><<<SNB, SBS, 0, s2>>>();
    place_set_kernel<1><<<cb, 256, 0, s2>>>(e1, E);
    cudaEventRecord(evB, s2);

    // main: layer-1 CSR + layer 1
    count_set_kernel<0><<<cb, 256>>>(e0, E);
    scan_set_kernel<0><<<SNB, SBS>>>();
    place_set_kernel<0><<<cb, 256>>>(e0, E);
    gather_kernel<0><<<gb, 256>>>(xh);
    dense_kernel<true, false><<<db, 256, dsmem>>>(x, W1, b1, R1, h4, n_nodes);

    // join layer-2 CSR, then layer 2
    cudaStreamWaitEvent(0, evB, 0);
    gather_kernel<1><<<gb, 256>>>(hh);
    dense_kernel<false, true><<<db, 256, dsmem>>>(h4, W2, b2, R2, out, n_nodes);
}